// round 6
// baseline (speedup 1.0000x reference)
#include <cuda_runtime.h>
#include <cuda_bf16.h>

// Problem constants (match reference)
#define NXg 2048
#define NYg 2048
#define INV_H  2048.0f   // 1/hx = 1/hy
#define INV_2H 1024.0f   // 1/(2hx)

#define ROWS_PER_THREAD 4
#define TPB 128          // 4 blocks in x cover 512 quads/row

__global__ void zero_out_kernel(float* out) {
    out[0] = 0.0f;
}

__global__ __launch_bounds__(TPB)
void flow_energy_kernel(const float* __restrict__ phi, float* __restrict__ out) {
    const int quad = blockIdx.x * TPB + threadIdx.x;   // column quad index (0..511)
    const int j0   = quad * 4;                          // first column of this quad
    const int r0   = blockIdx.y * ROWS_PER_THREAD;      // first row of this tile
    const int qstride = NYg / 4;

    const float4* __restrict__ phi4 = reinterpret_cast<const float4*>(phi);

    // Front-batched loads: rows r0-1 .. r0+ROWS (row-clamped; clamped rows are
    // only consumed by one-sided branches where they drop out).
    float4 v[ROWS_PER_THREAD + 2];
    #pragma unroll
    for (int i = 0; i < ROWS_PER_THREAD + 2; i++) {
        int r = r0 - 1 + i;
        r = (r < 0) ? 0 : ((r > NXg - 1) ? NXg - 1 : r);
        v[i] = phi4[r * qstride + quad];
    }

    const int  lane       = threadIdx.x & 31;
    const bool left_edge  = (j0 == 0);
    const bool right_edge = (j0 + 4 == NYg);

    float acc = 0.0f;

    #pragma unroll
    for (int rr = 0; rr < ROWS_PER_THREAD; rr++) {
        const int r = r0 + rr;
        const float4 prev = v[rr];
        const float4 cur  = v[rr + 1];
        const float4 next = v[rr + 2];

        // ---- vx (row-direction gradient); sign irrelevant (squared) ----
        float vx0, vx1, vx2, vx3;
        if (r == 0) {
            vx0 = (next.x - cur.x) * INV_H;
            vx1 = (next.y - cur.y) * INV_H;
            vx2 = (next.z - cur.z) * INV_H;
            vx3 = (next.w - cur.w) * INV_H;
        } else if (r == NXg - 1) {
            vx0 = (cur.x - prev.x) * INV_H;
            vx1 = (cur.y - prev.y) * INV_H;
            vx2 = (cur.z - prev.z) * INV_H;
            vx3 = (cur.w - prev.w) * INV_H;
        } else {
            vx0 = (next.x - prev.x) * INV_2H;
            vx1 = (next.y - prev.y) * INV_2H;
            vx2 = (next.z - prev.z) * INV_2H;
            vx3 = (next.w - prev.w) * INV_2H;
        }

        // ---- vy (column-direction gradient) ----
        // Neighbors from adjacent lanes' registers; warp-edge lanes use a
        // predicated 1-wavefront scalar load.
        float l  = __shfl_up_sync(0xFFFFFFFFu, cur.w, 1);
        float rt = __shfl_down_sync(0xFFFFFFFFu, cur.x, 1);
        if (lane == 0 && !left_edge)
            l = __ldg(&phi[r * NYg + j0 - 1]);
        if (lane == 31 && !right_edge)
            rt = __ldg(&phi[r * NYg + j0 + 4]);

        float vy0 = left_edge  ? (cur.y - cur.x) * INV_H : (cur.y - l) * INV_2H;
        float vy1 = (cur.z - cur.x) * INV_2H;
        float vy2 = (cur.w - cur.y) * INV_2H;
        float vy3 = right_edge ? (cur.w - cur.z) * INV_H : (rt - cur.z) * INV_2H;

        acc += vx0 * vx0 + vx1 * vx1 + vx2 * vx2 + vx3 * vx3;
        acc += vy0 * vy0 + vy1 * vy1 + vy2 * vy2 + vy3 * vy3;
    }

    // ---- warp reduce ----
    #pragma unroll
    for (int o = 16; o > 0; o >>= 1)
        acc += __shfl_xor_sync(0xFFFFFFFFu, acc, o);

    // ---- block reduce ----
    __shared__ float warp_sums[TPB / 32];
    const int wid = threadIdx.x >> 5;
    if (lane == 0) warp_sums[wid] = acc;
    __syncthreads();

    if (wid == 0) {
        float s = (lane < TPB / 32) ? warp_sums[lane] : 0.0f;
        #pragma unroll
        for (int o = 2; o > 0; o >>= 1)
            s += __shfl_xor_sync(0xFFFFFFFFu, s, o);
        if (lane == 0)
            atomicAdd(out, 0.5f * s);
    }
}

extern "C" void kernel_launch(void* const* d_in, const int* in_sizes, int n_in,
                              void* d_out, int out_size) {
    // d_in[0] = pos (unused), d_in[1] = potential_field [2048*2048] fp32
    const float* phi = (const float*)d_in[1];
    float* out = (float*)d_out;

    zero_out_kernel<<<1, 1>>>(out);

    dim3 grid(NYg / 4 / TPB, NXg / ROWS_PER_THREAD);  // (4, 512) = 2048 blocks
    flow_energy_kernel<<<grid, TPB>>>(phi, out);
}

// round 8
// speedup vs baseline: 1.1701x; 1.1701x over previous
#include <cuda_runtime.h>
#include <cuda_bf16.h>
#include <cstdint>

// Problem constants (match reference)
#define NXg 2048
#define NYg 2048
#define INV_H  2048.0f   // 1/hx = 1/hy
#define INV_2H 1024.0f   // 1/(2hx)

#define ROWS_PER_CTA 4
#define TPB 256
#define ROW_FLOATS NYg
#define ROW_BYTES (NYg * 4)          // 8192
#define QPR (NYg / 4)                // 512 float4 quads per row
#define SMEM_BYTES (6 * ROW_BYTES)   // 49152 (opt-in via cudaFuncSetAttribute)

__global__ void zero_out_kernel(float* out) {
    out[0] = 0.0f;
}

__device__ __forceinline__ uint32_t smem_u32(const void* p) {
    uint32_t a;
    asm("{ .reg .u64 t; cvta.to.shared.u64 t, %1; cvt.u32.u64 %0, t; }"
        : "=r"(a) : "l"(p));
    return a;
}

__global__ __launch_bounds__(TPB)
void flow_energy_kernel(const float* __restrict__ phi, float* __restrict__ out) {
    extern __shared__ float srows[];               // 6 rows x 2048 floats
    __shared__ __align__(8) unsigned long long mbar;

    const int tid = threadIdx.x;
    const int r0  = blockIdx.x * ROWS_PER_CTA;

    // Rows to fetch: [r0-1, r0+4] clamped. Row r lives at slot (r - (r0-1)).
    int lo = r0 - 1;             if (lo < 0)        lo = 0;
    int hi = r0 + ROWS_PER_CTA;  if (hi > NXg - 1)  hi = NXg - 1;
    const int      slot0 = lo - (r0 - 1);           // 0 or 1
    const uint32_t bytes = (uint32_t)(hi - lo + 1) * ROW_BYTES;

    const uint32_t mb  = smem_u32(&mbar);
    const uint32_t dst = smem_u32(srows) + (uint32_t)slot0 * ROW_BYTES;
    const float*   src = phi + (size_t)lo * ROW_FLOATS;

    if (tid == 0)
        asm volatile("mbarrier.init.shared.b64 [%0], %1;" :: "r"(mb), "r"(1u) : "memory");
    __syncthreads();

    if (tid == 0) {
        asm volatile("mbarrier.arrive.expect_tx.shared.b64 _, [%0], %1;"
                     :: "r"(mb), "r"(bytes) : "memory");
        // One contiguous bulk copy: sequential address stream to the MC.
        asm volatile(
            "cp.async.bulk.shared::cta.global.mbarrier::complete_tx::bytes [%0], [%1], %2, [%3];"
            :: "r"(dst), "l"(src), "r"(bytes), "r"(mb) : "memory");
    }

    // All threads wait for the bulk copy (HW-sleep try_wait).
    {
        uint32_t done;
        asm volatile(
            "{\n\t.reg .pred p;\n\t"
            "mbarrier.try_wait.parity.acquire.cta.shared::cta.b64 p, [%1], %2;\n\t"
            "selp.b32 %0, 1, 0, p;\n\t}"
            : "=r"(done) : "r"(mb), "r"(0u) : "memory");
        if (!done) {
            asm volatile(
                "{\n\t.reg .pred P1;\n\t"
                "WL_%=:\n\t"
                "mbarrier.try_wait.parity.acquire.cta.shared::cta.b64 P1, [%0], %1, 0x989680;\n\t"
                "@P1 bra.uni WD_%=;\n\t"
                "bra.uni WL_%=;\n\t"
                "WD_%=:\n\t}"
                :: "r"(mb), "r"(0u) : "memory");
        }
    }

    // ---- compute from smem ----
    const float4* row4 = reinterpret_cast<const float4*>(srows);
    float acc = 0.0f;

    #pragma unroll
    for (int s = 0; s < QPR / TPB; s++) {          // 2 column strips per thread
        const int  quad = tid + s * TPB;           // 0..511
        const int  j0   = quad * 4;
        const bool left_edge  = (j0 == 0);
        const bool right_edge = (j0 + 4 == NYg);

        // Rolling rows (slots rr, rr+1, rr+2 = rows r-1, r, r+1).
        float4 prev = row4[0 * QPR + quad];        // garbage iff r0==0 (branch discards)
        float4 cur  = row4[1 * QPR + quad];

        #pragma unroll
        for (int rr = 0; rr < ROWS_PER_CTA; rr++) {
            const int r = r0 + rr;
            float4 next = row4[(rr + 2) * QPR + quad];  // garbage iff r==NXg-1 (discarded)

            // ---- vx ----
            float vx0, vx1, vx2, vx3;
            if (r == 0) {
                vx0 = (next.x - cur.x) * INV_H;
                vx1 = (next.y - cur.y) * INV_H;
                vx2 = (next.z - cur.z) * INV_H;
                vx3 = (next.w - cur.w) * INV_H;
            } else if (r == NXg - 1) {
                vx0 = (cur.x - prev.x) * INV_H;
                vx1 = (cur.y - prev.y) * INV_H;
                vx2 = (cur.z - prev.z) * INV_H;
                vx3 = (cur.w - prev.w) * INV_H;
            } else {
                vx0 = (next.x - prev.x) * INV_2H;
                vx1 = (next.y - prev.y) * INV_2H;
                vx2 = (next.z - prev.z) * INV_2H;
                vx3 = (next.w - prev.w) * INV_2H;
            }

            // ---- vy ---- (neighbor scalars straight from smem)
            const float* crow = srows + (rr + 1) * ROW_FLOATS;
            float l  = left_edge  ? 0.0f : crow[j0 - 1];
            float rt = right_edge ? 0.0f : crow[j0 + 4];

            float vy0 = left_edge  ? (cur.y - cur.x) * INV_H : (cur.y - l) * INV_2H;
            float vy1 = (cur.z - cur.x) * INV_2H;
            float vy2 = (cur.w - cur.y) * INV_2H;
            float vy3 = right_edge ? (cur.w - cur.z) * INV_H : (rt - cur.z) * INV_2H;

            acc += vx0 * vx0 + vx1 * vx1 + vx2 * vx2 + vx3 * vx3;
            acc += vy0 * vy0 + vy1 * vy1 + vy2 * vy2 + vy3 * vy3;

            prev = cur;
            cur  = next;
        }
    }

    // ---- warp reduce ----
    #pragma unroll
    for (int o = 16; o > 0; o >>= 1)
        acc += __shfl_xor_sync(0xFFFFFFFFu, acc, o);

    // ---- block reduce ----
    __shared__ float warp_sums[TPB / 32];
    const int lane = tid & 31;
    const int wid  = tid >> 5;
    if (lane == 0) warp_sums[wid] = acc;
    __syncthreads();

    if (wid == 0) {
        float v = (lane < TPB / 32) ? warp_sums[lane] : 0.0f;
        #pragma unroll
        for (int o = 4; o > 0; o >>= 1)
            v += __shfl_xor_sync(0xFFFFFFFFu, v, o);
        if (lane == 0)
            atomicAdd(out, 0.5f * v);
    }
}

extern "C" void kernel_launch(void* const* d_in, const int* in_sizes, int n_in,
                              void* d_out, int out_size) {
    // d_in[0] = pos (unused), d_in[1] = potential_field [2048*2048] fp32
    const float* phi = (const float*)d_in[1];
    float* out = (float*)d_out;

    // Opt in to >48KB dynamic smem (static smem uses a few bytes on top of the
    // 48KB dynamic request, so the default limit rejects the launch).
    cudaFuncSetAttribute(flow_energy_kernel,
                         cudaFuncAttributeMaxDynamicSharedMemorySize, SMEM_BYTES);

    zero_out_kernel<<<1, 1>>>(out);

    flow_energy_kernel<<<NXg / ROWS_PER_CTA, TPB, SMEM_BYTES>>>(phi, out);
}

// round 9
// speedup vs baseline: 1.2390x; 1.0588x over previous
#include <cuda_runtime.h>
#include <cuda_bf16.h>
#include <cstdint>

// Problem constants (match reference)
#define NXg 2048
#define NYg 2048
#define INV_H  2048.0f   // 1/hx = 1/hy
#define INV_2H 1024.0f   // 1/(2hx)

#define ROWS_OWNED 8                  // rows computed per CTA
#define SLOTS 10                      // rows r0-1 .. r0+8 resident in smem
#define TPB 512                       // one column-quad per thread
#define ROW_FLOATS NYg
#define ROW_BYTES (NYg * 4)           // 8192
#define QPR (NYg / 4)                 // 512 float4 quads per row
#define SMEM_BYTES (SLOTS * ROW_BYTES) // 81920

__global__ void zero_out_kernel(float* out) {
    out[0] = 0.0f;
}

__device__ __forceinline__ uint32_t smem_u32(const void* p) {
    uint32_t a;
    asm("{ .reg .u64 t; cvta.to.shared.u64 t, %1; cvt.u32.u64 %0, t; }"
        : "=r"(a) : "l"(p));
    return a;
}

__device__ __forceinline__ void mbar_wait(uint32_t mb) {
    uint32_t done;
    asm volatile(
        "{\n\t.reg .pred p;\n\t"
        "mbarrier.try_wait.parity.acquire.cta.shared::cta.b64 p, [%1], %2;\n\t"
        "selp.b32 %0, 1, 0, p;\n\t}"
        : "=r"(done) : "r"(mb), "r"(0u) : "memory");
    if (!done) {
        asm volatile(
            "{\n\t.reg .pred P1;\n\t"
            "WL_%=:\n\t"
            "mbarrier.try_wait.parity.acquire.cta.shared::cta.b64 P1, [%0], %1, 0x989680;\n\t"
            "@P1 bra.uni WD_%=;\n\t"
            "bra.uni WL_%=;\n\t"
            "WD_%=:\n\t}"
            :: "r"(mb), "r"(0u) : "memory");
    }
}

__global__ __launch_bounds__(TPB)
void flow_energy_kernel(const float* __restrict__ phi, float* __restrict__ out) {
    extern __shared__ float srows[];                 // 10 rows x 2048 floats
    __shared__ __align__(8) unsigned long long mbar[2];

    const int tid = threadIdx.x;
    const int r0  = blockIdx.x * ROWS_OWNED;

    // Slab 0: rows r0-1 .. r0+4 (clamped at top)  -> slots 0..5
    // Slab 1: rows r0+5 .. r0+8 (clamped at bot)  -> slots 6..9
    // Row r lives at slot (r - (r0-1)).
    int lo0 = r0 - 1;  if (lo0 < 0) lo0 = 0;
    const int hi0 = r0 + 4;                          // r0 <= 2040 -> hi0 <= 2044
    const int lo1 = r0 + 5;
    int hi1 = r0 + 8;  if (hi1 > NXg - 1) hi1 = NXg - 1;

    const uint32_t bytes0 = (uint32_t)(hi0 - lo0 + 1) * ROW_BYTES;
    const uint32_t bytes1 = (uint32_t)(hi1 - lo1 + 1) * ROW_BYTES;

    const uint32_t mb0 = smem_u32(&mbar[0]);
    const uint32_t mb1 = smem_u32(&mbar[1]);
    const uint32_t sb  = smem_u32(srows);
    const uint32_t dst0 = sb + (uint32_t)(lo0 - (r0 - 1)) * ROW_BYTES;
    const uint32_t dst1 = sb + 6u * ROW_BYTES;

    if (tid == 0) {
        asm volatile("mbarrier.init.shared.b64 [%0], %1;" :: "r"(mb0), "r"(1u) : "memory");
        asm volatile("mbarrier.init.shared.b64 [%0], %1;" :: "r"(mb1), "r"(1u) : "memory");
    }
    __syncthreads();

    if (tid == 0) {
        // Issue BOTH bulk copies immediately: deep, continuous in-flight stream.
        asm volatile("mbarrier.arrive.expect_tx.shared.b64 _, [%0], %1;"
                     :: "r"(mb0), "r"(bytes0) : "memory");
        asm volatile(
            "cp.async.bulk.shared::cta.global.mbarrier::complete_tx::bytes [%0], [%1], %2, [%3];"
            :: "r"(dst0), "l"(phi + (size_t)lo0 * ROW_FLOATS), "r"(bytes0), "r"(mb0) : "memory");
        asm volatile("mbarrier.arrive.expect_tx.shared.b64 _, [%0], %1;"
                     :: "r"(mb1), "r"(bytes1) : "memory");
        asm volatile(
            "cp.async.bulk.shared::cta.global.mbarrier::complete_tx::bytes [%0], [%1], %2, [%3];"
            :: "r"(dst1), "l"(phi + (size_t)lo1 * ROW_FLOATS), "r"(bytes1), "r"(mb1) : "memory");
    }

    const float4* row4 = reinterpret_cast<const float4*>(srows);
    const int  quad = tid;                           // 0..511
    const int  j0   = quad * 4;
    const bool left_edge  = (j0 == 0);
    const bool right_edge = (j0 + 4 == NYg);

    float acc = 0.0f;

    // Phase 0 (rows r0..r0+3, slots 0..5) then Phase 1 (rows r0+4..r0+7, slots 4..9).
    #pragma unroll
    for (int phase = 0; phase < 2; phase++) {
        mbar_wait(phase == 0 ? mb0 : mb1);

        const int base = phase * 4;
        float4 prev = row4[(base + 0) * QPR + quad];
        float4 cur  = row4[(base + 1) * QPR + quad];

        #pragma unroll
        for (int k = 0; k < 4; k++) {
            const int rr = base + k;                 // 0..7
            const int r  = r0 + rr;
            float4 next = row4[(rr + 2) * QPR + quad]; // garbage iff r==NXg-1 (discarded)

            // ---- vx ----
            float vx0, vx1, vx2, vx3;
            if (r == 0) {
                vx0 = (next.x - cur.x) * INV_H;
                vx1 = (next.y - cur.y) * INV_H;
                vx2 = (next.z - cur.z) * INV_H;
                vx3 = (next.w - cur.w) * INV_H;
            } else if (r == NXg - 1) {
                vx0 = (cur.x - prev.x) * INV_H;
                vx1 = (cur.y - prev.y) * INV_H;
                vx2 = (cur.z - prev.z) * INV_H;
                vx3 = (cur.w - prev.w) * INV_H;
            } else {
                vx0 = (next.x - prev.x) * INV_2H;
                vx1 = (next.y - prev.y) * INV_2H;
                vx2 = (next.z - prev.z) * INV_2H;
                vx3 = (next.w - prev.w) * INV_2H;
            }

            // ---- vy ---- (neighbor scalars straight from smem)
            const float* crow = srows + (rr + 1) * ROW_FLOATS;
            float l  = left_edge  ? 0.0f : crow[j0 - 1];
            float rt = right_edge ? 0.0f : crow[j0 + 4];

            float vy0 = left_edge  ? (cur.y - cur.x) * INV_H : (cur.y - l) * INV_2H;
            float vy1 = (cur.z - cur.x) * INV_2H;
            float vy2 = (cur.w - cur.y) * INV_2H;
            float vy3 = right_edge ? (cur.w - cur.z) * INV_H : (rt - cur.z) * INV_2H;

            acc += vx0 * vx0 + vx1 * vx1 + vx2 * vx2 + vx3 * vx3;
            acc += vy0 * vy0 + vy1 * vy1 + vy2 * vy2 + vy3 * vy3;

            prev = cur;
            cur  = next;
        }
    }

    // ---- warp reduce ----
    #pragma unroll
    for (int o = 16; o > 0; o >>= 1)
        acc += __shfl_xor_sync(0xFFFFFFFFu, acc, o);

    // ---- block reduce ----
    __shared__ float warp_sums[TPB / 32];
    const int lane = tid & 31;
    const int wid  = tid >> 5;
    if (lane == 0) warp_sums[wid] = acc;
    __syncthreads();

    if (wid == 0) {
        float v = (lane < TPB / 32) ? warp_sums[lane] : 0.0f;
        #pragma unroll
        for (int o = 8; o > 0; o >>= 1)
            v += __shfl_xor_sync(0xFFFFFFFFu, v, o);
        if (lane == 0)
            atomicAdd(out, 0.5f * v);
    }
}

extern "C" void kernel_launch(void* const* d_in, const int* in_sizes, int n_in,
                              void* d_out, int out_size) {
    // d_in[0] = pos (unused), d_in[1] = potential_field [2048*2048] fp32
    const float* phi = (const float*)d_in[1];
    float* out = (float*)d_out;

    cudaFuncSetAttribute(flow_energy_kernel,
                         cudaFuncAttributeMaxDynamicSharedMemorySize, SMEM_BYTES);

    zero_out_kernel<<<1, 1>>>(out);

    flow_energy_kernel<<<NXg / ROWS_OWNED, TPB, SMEM_BYTES>>>(phi, out);  // 256 CTAs
}

// round 10
// speedup vs baseline: 1.2435x; 1.0037x over previous
#include <cuda_runtime.h>
#include <cuda_bf16.h>
#include <cstdint>

// Problem constants (match reference)
#define NXg 2048
#define NYg 2048
#define INV_H  2048.0f   // 1/hx = 1/hy
#define INV_2H 1024.0f   // 1/(2hx)

#define RPT 4                          // rows per block
#define TPB 512                        // one column-quad per thread
#define ROW_FLOATS NYg
#define ROW_BYTES (NYg * 4)            // 8192
#define QPR (NYg / 4)                  // 512
#define SMEM_BYTES (6 * ROW_BYTES)     // 49152 (TMA-path blocks)

__global__ void zero_out_kernel(float* out) {
    out[0] = 0.0f;
}

__device__ __forceinline__ uint32_t smem_u32(const void* p) {
    uint32_t a;
    asm("{ .reg .u64 t; cvta.to.shared.u64 t, %1; cvt.u32.u64 %0, t; }"
        : "=r"(a) : "l"(p));
    return a;
}

__device__ __forceinline__ void mbar_wait(uint32_t mb) {
    uint32_t done;
    asm volatile(
        "{\n\t.reg .pred p;\n\t"
        "mbarrier.try_wait.parity.acquire.cta.shared::cta.b64 p, [%1], %2;\n\t"
        "selp.b32 %0, 1, 0, p;\n\t}"
        : "=r"(done) : "r"(mb), "r"(0u) : "memory");
    if (!done) {
        asm volatile(
            "{\n\t.reg .pred P1;\n\t"
            "WL_%=:\n\t"
            "mbarrier.try_wait.parity.acquire.cta.shared::cta.b64 P1, [%0], %1, 0x989680;\n\t"
            "@P1 bra.uni WD_%=;\n\t"
            "bra.uni WL_%=;\n\t"
            "WD_%=:\n\t}"
            :: "r"(mb), "r"(0u) : "memory");
    }
}

// Shared stencil body: given prev/cur/next quads for row r plus left/right
// neighbor scalars, accumulate |v|^2 contributions.
__device__ __forceinline__ float stencil_acc(
    int r, float4 prev, float4 cur, float4 next,
    float l, float rt, bool left_edge, bool right_edge)
{
    float vx0, vx1, vx2, vx3;
    if (r == 0) {
        vx0 = (next.x - cur.x) * INV_H;
        vx1 = (next.y - cur.y) * INV_H;
        vx2 = (next.z - cur.z) * INV_H;
        vx3 = (next.w - cur.w) * INV_H;
    } else if (r == NXg - 1) {
        vx0 = (cur.x - prev.x) * INV_H;
        vx1 = (cur.y - prev.y) * INV_H;
        vx2 = (cur.z - prev.z) * INV_H;
        vx3 = (cur.w - prev.w) * INV_H;
    } else {
        vx0 = (next.x - prev.x) * INV_2H;
        vx1 = (next.y - prev.y) * INV_2H;
        vx2 = (next.z - prev.z) * INV_2H;
        vx3 = (next.w - prev.w) * INV_2H;
    }

    float vy0 = left_edge  ? (cur.y - cur.x) * INV_H : (cur.y - l) * INV_2H;
    float vy1 = (cur.z - cur.x) * INV_2H;
    float vy2 = (cur.w - cur.y) * INV_2H;
    float vy3 = right_edge ? (cur.w - cur.z) * INV_H : (rt - cur.z) * INV_2H;

    return vx0 * vx0 + vx1 * vx1 + vx2 * vx2 + vx3 * vx3 +
           vy0 * vy0 + vy1 * vy1 + vy2 * vy2 + vy3 * vy3;
}

__global__ __launch_bounds__(TPB)
void flow_energy_kernel(const float* __restrict__ phi, float* __restrict__ out) {
    extern __shared__ float srows[];                 // 6 rows (TMA-path blocks only)
    __shared__ __align__(8) unsigned long long mbar;
    __shared__ float warp_sums[TPB / 32];

    const int tid  = threadIdx.x;
    const int blk  = blockIdx.x;
    const int r0   = blk * RPT;
    const int quad = tid;                             // 0..511
    const int j0   = quad * 4;
    const int lane = tid & 31;
    const bool left_edge  = (j0 == 0);
    const bool right_edge = (j0 + 4 == NYg);

    float acc = 0.0f;

    if (blk & 1) {
        // ================= LDG path (register stencil, R4 body) =============
        const float4* __restrict__ phi4 = reinterpret_cast<const float4*>(phi);
        float4 v[RPT + 2];
        #pragma unroll
        for (int i = 0; i < RPT + 2; i++) {
            int r = r0 - 1 + i;
            r = (r < 0) ? 0 : ((r > NXg - 1) ? NXg - 1 : r);
            v[i] = phi4[r * QPR + quad];
        }

        #pragma unroll
        for (int rr = 0; rr < RPT; rr++) {
            const int r = r0 + rr;
            const float4 cur = v[rr + 1];

            float l  = __shfl_up_sync(0xFFFFFFFFu, cur.w, 1);
            float rt = __shfl_down_sync(0xFFFFFFFFu, cur.x, 1);
            if (lane == 0 && !left_edge)
                l = __ldg(&phi[r * NYg + j0 - 1]);
            if (lane == 31 && !right_edge)
                rt = __ldg(&phi[r * NYg + j0 + 4]);

            acc += stencil_acc(r, v[rr], cur, v[rr + 2], l, rt,
                               left_edge, right_edge);
        }
    } else {
        // ================= TMA path (bulk copy -> smem stencil) =============
        int lo = r0 - 1;       if (lo < 0)       lo = 0;
        int hi = r0 + RPT;     if (hi > NXg - 1) hi = NXg - 1;
        const uint32_t bytes = (uint32_t)(hi - lo + 1) * ROW_BYTES;
        const uint32_t mb    = smem_u32(&mbar);
        const uint32_t dst   = smem_u32(srows) + (uint32_t)(lo - (r0 - 1)) * ROW_BYTES;

        if (tid == 0) {
            asm volatile("mbarrier.init.shared.b64 [%0], %1;"
                         :: "r"(mb), "r"(1u) : "memory");
        }
        __syncthreads();
        if (tid == 0) {
            asm volatile("mbarrier.arrive.expect_tx.shared.b64 _, [%0], %1;"
                         :: "r"(mb), "r"(bytes) : "memory");
            asm volatile(
                "cp.async.bulk.shared::cta.global.mbarrier::complete_tx::bytes [%0], [%1], %2, [%3];"
                :: "r"(dst), "l"(phi + (size_t)lo * ROW_FLOATS), "r"(bytes), "r"(mb)
                : "memory");
        }
        mbar_wait(mb);

        const float4* row4 = reinterpret_cast<const float4*>(srows);
        float4 prev = row4[0 * QPR + quad];   // garbage iff r0==0 (branch discards)
        float4 cur  = row4[1 * QPR + quad];

        #pragma unroll
        for (int rr = 0; rr < RPT; rr++) {
            const int r = r0 + rr;
            float4 next = row4[(rr + 2) * QPR + quad];

            const float* crow = srows + (rr + 1) * ROW_FLOATS;
            float l  = left_edge  ? 0.0f : crow[j0 - 1];
            float rt = right_edge ? 0.0f : crow[j0 + 4];

            acc += stencil_acc(r, prev, cur, next, l, rt, left_edge, right_edge);

            prev = cur;
            cur  = next;
        }
    }

    // ---- warp reduce ----
    #pragma unroll
    for (int o = 16; o > 0; o >>= 1)
        acc += __shfl_xor_sync(0xFFFFFFFFu, acc, o);

    // ---- block reduce ----
    const int wid = tid >> 5;
    if (lane == 0) warp_sums[wid] = acc;
    __syncthreads();

    if (wid == 0) {
        float v = (lane < TPB / 32) ? warp_sums[lane] : 0.0f;
        #pragma unroll
        for (int o = 8; o > 0; o >>= 1)
            v += __shfl_xor_sync(0xFFFFFFFFu, v, o);
        if (lane == 0)
            atomicAdd(out, 0.5f * v);
    }
}

extern "C" void kernel_launch(void* const* d_in, const int* in_sizes, int n_in,
                              void* d_out, int out_size) {
    // d_in[0] = pos (unused), d_in[1] = potential_field [2048*2048] fp32
    const float* phi = (const float*)d_in[1];
    float* out = (float*)d_out;

    cudaFuncSetAttribute(flow_energy_kernel,
                         cudaFuncAttributeMaxDynamicSharedMemorySize, SMEM_BYTES);

    zero_out_kernel<<<1, 1>>>(out);

    flow_energy_kernel<<<NXg / RPT, TPB, SMEM_BYTES>>>(phi, out);  // 512 CTAs
}